// round 7
// baseline (speedup 1.0000x reference)
#include <cuda_runtime.h>

// SpringMass: B=4096 independent 2-state linear ODEs, T=4096 RK4 steps each.
// Affine scan over time (pass1 compose / pass2 block scan / pass3 replay),
// two 2048-step halves with carried (v,x) state.
//
// R5 change: packed f32x2 (FFMA2) math in pass1/pass3. Pass1 composes in
// REVERSE time order (M <- M∘s) so per-step scalars come from the step map,
// evaluated as splat polynomials on (k,k) — no lane-extract movs. Pass3 uses
// column-packed coefficients (two matrix entries per FMA). Smem swizzle
// replaced by stride-9 float4 padding (1 IMAD vs 3-op XOR path).

#define T_LEN  4096
#define NTHR   128
#define HALF   (T_LEN / 2)
#define F4C    8                  // input float4 per chunk per half
#define O4C    4                  // output float4 per chunk per half
#define SSTRIDE 9                 // padded float4 stride per chunk

typedef unsigned long long u64;   // f32x2 carrier

#define FMA2(d,a,b,c) asm("fma.rn.f32x2 %0, %1, %2, %3;" : "=l"(d) : "l"(a), "l"(b), "l"(c))
#define MUL2(d,a,b)   asm("mul.rn.f32x2 %0, %1, %2;"     : "=l"(d) : "l"(a), "l"(b))
#define PACK2(d,lo,hi)   asm("mov.b64 %0, {%1, %2};" : "=l"(d) : "f"(lo), "f"(hi))
#define UNPACK2(lo,hi,s) asm("mov.b64 {%0, %1}, %2;" : "=f"(lo), "=f"(hi) : "l"(s))

namespace sm_consts {
constexpr double Cd = 0.1, hd = 0.005, dd = 0.01, wd = dd / 6.0;
constexpr double P2   = 1.0 - hd * Cd;
constexpr double A2c  = -Cd * P2;
constexpr double A2k  = -hd;
constexpr double B2k  = Cd * hd - 1.0;
constexpr double G2   = 1.0 - Cd * hd;
constexpr double Va3c = 1.0 + hd * A2c;
constexpr double Va3k = hd * A2k;
constexpr double Vb3k = hd * B2k;
constexpr double Vg3  = hd * G2;
constexpr double Xa3v = hd * P2;
constexpr double Xa3xk = -hd * hd;
constexpr double Xa3f  = hd * hd;
constexpr double A3c  = -Cd * Va3c;
constexpr double A3k  = -Cd * Va3k - Xa3v;
constexpr double B3k  = -Cd * Vb3k - 1.0;
constexpr double B3k2 = -Xa3xk;
constexpr double G3c  = 1.0 - Cd * Vg3;
constexpr double G3k  = -Xa3f;
constexpr double Va4c = 1.0 + dd * A3c;
constexpr double Va4k = dd * A3k;
constexpr double Vb4k  = dd * B3k;
constexpr double Vb4k2 = dd * B3k2;
constexpr double Vg4c  = dd * G3c;
constexpr double Vg4k  = dd * G3k;
constexpr double Xa4vc = dd * Va3c, Xa4vk = dd * Va3k;
constexpr double Xa4xk = dd * Vb3k;
constexpr double Xa4f  = dd * Vg3;
constexpr double A4c  = -Cd * Va4c;
constexpr double A4k  = -Cd * Va4k - Xa4vc;
constexpr double A4k2 = -Xa4vk;
constexpr double B4k  = -Cd * Vb4k - 1.0;
constexpr double B4k2 = -Cd * Vb4k2 - Xa4xk;
constexpr double G4c  = 1.0 - Cd * Vg4c;
constexpr double G4k  = -Cd * Vg4k - Xa4f;

// Step map polynomials in k:
// A11 = K110 + K111 k + K112 k^2     A12 = K121 k + K122 k^2
// A21 = K210 + K211 k                A22 = 1 + K221 k + K222 k^2
// g1  = KG10 + KG11 k                g2  = KG20 + KG21 k   (b = F*g)
constexpr float K110 = (float)(1.0 + wd * (-Cd + 2*A2c + 2*A3c + A4c));
constexpr float K111 = (float)(wd * (2*A2k + 2*A3k + A4k));
constexpr float K112 = (float)(wd * A4k2);
constexpr float K121 = (float)(wd * (-1.0 + 2*B2k + 2*B3k + B4k));
constexpr float K122 = (float)(wd * (2*B3k2 + B4k2));
constexpr float KG10 = (float)(wd * (1.0 + 2*G2 + 2*G3c + G4c));
constexpr float KG11 = (float)(wd * (2*G3k + G4k));
constexpr float K210 = (float)(wd * (1.0 + 2*P2 + 2*Va3c + Va4c));
constexpr float K211 = (float)(wd * (2*Va3k + Va4k));
constexpr float K221 = (float)(wd * (-2.0*hd + 2*Vb3k + Vb4k));
constexpr float K222 = (float)(wd * Vb4k2);
constexpr float KG20 = (float)(wd * (2.0*hd + 2*Vg3 + Vg4c));
constexpr float KG21 = (float)(wd * Vg4k);
constexpr float CF   = 0.1f;
}  // namespace sm_consts

// ---------------- scalar Aff (scan phase only) ----------------
struct Aff { float a11, a12, a21, a22, b1, b2; };

__device__ __forceinline__ Aff compose(const Aff& n, const Aff& o) {
    Aff r;
    r.a11 = fmaf(n.a11, o.a11, n.a12 * o.a21);
    r.a12 = fmaf(n.a11, o.a12, n.a12 * o.a22);
    r.a21 = fmaf(n.a21, o.a11, n.a22 * o.a21);
    r.a22 = fmaf(n.a21, o.a12, n.a22 * o.a22);
    r.b1  = fmaf(n.a11, o.b1, fmaf(n.a12, o.b2, n.b1));
    r.b2  = fmaf(n.a21, o.b1, fmaf(n.a22, o.b2, n.b2));
    return r;
}

__device__ __forceinline__ Aff shfl_up_aff(const Aff& m, int off) {
    Aff r;
    r.a11 = __shfl_up_sync(0xffffffffu, m.a11, off);
    r.a12 = __shfl_up_sync(0xffffffffu, m.a12, off);
    r.a21 = __shfl_up_sync(0xffffffffu, m.a21, off);
    r.a22 = __shfl_up_sync(0xffffffffu, m.a22, off);
    r.b1  = __shfl_up_sync(0xffffffffu, m.b1,  off);
    r.b2  = __shfl_up_sync(0xffffffffu, m.b2,  off);
    return r;
}

__global__ void __launch_bounds__(NTHR, 9)
spring_scan_kernel(const float* __restrict__ in,
                   const float* __restrict__ vinit,
                   const float* __restrict__ xinit,
                   float* __restrict__ out) {
    using namespace sm_consts;
    __shared__ float4 buf[NTHR * SSTRIDE];   // 18 KB padded half-row tile
    __shared__ Aff wsum[NTHR / 32];

    const int b = blockIdx.x;
    const int l = threadIdx.x;
    const int lane = l & 31;
    const int w = l >> 5;

    const float4* gin  = reinterpret_cast<const float4*>(in + (long)b * T_LEN * 2);
    float4*       gout = reinterpret_cast<float4*>(out + (long)b * T_LEN);

    // ---- packed splat constants (pass1) ----
    u64 SC110, SC111, SC112, SC121, SC122, SC210, SC211, SC221, SC222, ONE2;
    PACK2(SC110, K110, K110); PACK2(SC111, K111, K111); PACK2(SC112, K112, K112);
    PACK2(SC121, K121, K121); PACK2(SC122, K122, K122);
    PACK2(SC210, K210, K210); PACK2(SC211, K211, K211);
    PACK2(SC221, K221, K221); PACK2(SC222, K222, K222);
    PACK2(ONE2, 1.0f, 1.0f);
    // ---- packed column constants (pass3) ----
    u64 CP0, CP1, CP2, CQ0, CQ1, CQ2, CG0, CG1;
    PACK2(CP0, K110, K210); PACK2(CP1, K111, K211); PACK2(CP2, K112, 0.0f);
    PACK2(CQ0, 0.0f, 1.0f); PACK2(CQ1, K121, K221); PACK2(CQ2, K122, K222);
    PACK2(CG0, KG10, KG20); PACK2(CG1, KG11, KG21);

    float vh = vinit[b], xh = xinit[b];    // state entering current half

#pragma unroll 1
    for (int half = 0; half < 2; half++) {
        const float4* gin_h  = gin  + half * (HALF / 2);   // 1024 f4 / half
        float4*       gout_h = gout + half * (HALF / 4);   // 512 f4 / half

        // ---- Stage: coalesced global -> padded smem ----
#pragma unroll
        for (int r = 0; r < F4C; r++) {
            int idx = r * NTHR + l;
            buf[(idx >> 3) * SSTRIDE + (idx & 7)] = gin_h[idx];
        }
        __syncthreads();

        // ---- Pass 1: chunk map, REVERSE time, M <- M ∘ s(step) ----
        // M column-packed: c1=(a11,a21), c2=(a12,a22), bb=(b1,b2)
        u64 Mc1, Mc2, Mbb;
        PACK2(Mc1, 1.0f, 0.0f); PACK2(Mc2, 0.0f, 1.0f); PACK2(Mbb, 0.0f, 0.0f);
#pragma unroll 4
        for (int o = F4C - 1; o >= 0; o--) {
            float4 d = buf[l * SSTRIDE + o];
            // within float4: later step (d.z,d.w) first
#pragma unroll
            for (int half4 = 0; half4 < 2; half4++) {
                float k = half4 ? d.x : d.z;
                float F = half4 ? d.y : d.w;
                u64 kk, t, s11, s12, s21, s22;
                PACK2(kk, k, k);
                FMA2(t, SC112, kk, SC111); FMA2(s11, t, kk, SC110);
                FMA2(t, SC122, kk, SC121); MUL2(s12, t, kk);
                FMA2(s21, SC211, kk, SC210);
                FMA2(t, SC222, kk, SC221); FMA2(s22, t, kk, ONE2);
                float g1 = fmaf(KG11, k, KG10);
                float g2 = fmaf(KG21, k, KG20);
                float b1 = F * g1, b2 = F * g2;
                u64 sb1, sb2;
                PACK2(sb1, b1, b1); PACK2(sb2, b2, b2);
                u64 nc1, nc2, nb;
                MUL2(t, Mc1, s11); FMA2(nc1, Mc2, s21, t);
                MUL2(t, Mc1, s12); FMA2(nc2, Mc2, s22, t);
                FMA2(t, Mc1, sb1, Mbb); FMA2(nb, Mc2, sb2, t);
                Mc1 = nc1; Mc2 = nc2; Mbb = nb;
            }
        }
        // unpack to scalar Aff for the scan
        Aff M;
        UNPACK2(M.a11, M.a21, Mc1);
        UNPACK2(M.a12, M.a22, Mc2);
        UNPACK2(M.b1,  M.b2,  Mbb);

        // ---- Pass 2: block-wide scan ----
#pragma unroll
        for (int off = 1; off < 32; off <<= 1) {
            Aff o = shfl_up_aff(M, off);
            if (lane >= off) M = compose(M, o);
        }

        if (lane == 31) wsum[w] = M;
        __syncthreads();

        Aff pre    = {1.f, 0.f, 0.f, 1.f, 0.f, 0.f};
        Aff preAll = {1.f, 0.f, 0.f, 1.f, 0.f, 0.f};
#pragma unroll
        for (int j = 0; j < NTHR / 32; j++) {
            if (j == w) pre = preAll;
            preAll = compose(wsum[j], preAll);
        }

        Aff eo = shfl_up_aff(M, 1);
        Aff excl;
        if (lane == 0) { excl.a11 = 1.f; excl.a12 = 0.f; excl.a21 = 0.f;
                         excl.a22 = 1.f; excl.b1 = 0.f;  excl.b2 = 0.f; }
        else           { excl = eo; }

        Aff tot = compose(excl, pre);   // exclusive prefix within half

        // state entering this thread's chunk
        float v0 = fmaf(tot.a11, vh, fmaf(tot.a12, xh, tot.b1));
        float x0 = fmaf(tot.a21, vh, fmaf(tot.a22, xh, tot.b2));

        // carry: state entering next half
        float vh2 = fmaf(preAll.a11, vh, fmaf(preAll.a12, xh, preAll.b1));
        float xh2 = fmaf(preAll.a21, vh, fmaf(preAll.a22, xh, preAll.b2));
        vh = vh2; xh = xh2;

        // ---- Pass 3: replay chunk (packed state), write xddot in place ----
        u64 st;                          // (v, x)
        PACK2(st, v0, x0);
#pragma unroll 2
        for (int j = 0; j < O4C; j++) {
            float4 d0 = buf[l * SSTRIDE + 2 * j];
            float4 d1 = buf[l * SSTRIDE + 2 * j + 1];
            float4 o4;
            float ks[4] = {d0.x, d0.z, d1.x, d1.z};
            float Fs[4] = {d0.y, d0.w, d1.y, d1.w};
            float res[4];
#pragma unroll
            for (int q = 0; q < 4; q++) {
                float k = ks[q], F = Fs[q];
                u64 kk, t, c1, c2, g, bb, FF;
                PACK2(kk, k, k);
                FMA2(t, CP2, kk, CP1); FMA2(c1, t, kk, CP0);   // (A11, A21)
                FMA2(t, CQ2, kk, CQ1); FMA2(c2, t, kk, CQ0);   // (A12, A22)
                FMA2(g, CG1, kk, CG0);                          // (g1, g2)
                PACK2(FF, F, F); MUL2(bb, FF, g);               // (b1, b2)
                float vv, xx;
                UNPACK2(vv, xx, st);
                u64 vs, xs;
                PACK2(vs, vv, vv); PACK2(xs, xx, xx);
                FMA2(t, c1, vs, bb); FMA2(st, c2, xs, t);       // s' = A s + b
                float v2, x2;
                UNPACK2(v2, x2, st);
                res[q] = fmaf(-k, x2, fmaf(-CF, v2, F));
            }
            o4.x = res[0]; o4.y = res[1]; o4.z = res[2]; o4.w = res[3];
            buf[l * SSTRIDE + j] = o4;   // overwrites consumed input slot j
        }
        __syncthreads();

        // ---- Drain: padded smem -> coalesced global store ----
#pragma unroll
        for (int r = 0; r < O4C; r++) {
            int idx = r * NTHR + l;
            gout_h[idx] = buf[(idx >> 2) * SSTRIDE + (idx & 3)];
        }
        __syncthreads();   // buf + wsum reuse in next half
    }
}

extern "C" void kernel_launch(void* const* d_in, const int* in_sizes, int n_in,
                              void* d_out, int out_size) {
    const float* in = (const float*)d_in[0];       // (B, T, 2) float32
    const float* vi = (const float*)d_in[1];       // (B, 1)
    const float* xi = (const float*)d_in[2];       // (B, 1)
    float* out = (float*)d_out;                    // (B, T, 1) float32
    const int B = in_sizes[1];                     // 4096
    spring_scan_kernel<<<B, NTHR>>>(in, vi, xi, out);
}

// round 8
// speedup vs baseline: 1.3698x; 1.3698x over previous
#include <cuda_runtime.h>

// SpringMass: B=4096 independent 2-state linear ODEs, T=4096 RK4 steps each.
// Affine scan over time (pass1 compose / pass2 block scan / pass3 replay),
// two 2048-step halves with carried (v,x) state. (R4 structure.)
//
// R8 change: Cayley-Hamilton coefficient evaluation. RK4 step matrix is the
// deg-4 Taylor of exp(dt*B), B=[[-C,-k],[1,0]], so A = alpha(k)*I + beta(k)*B
// with alpha quadratic and beta LINEAR in k. A21=beta, A22=alpha,
// A11=alpha-C*beta, A12=-k*beta => 2 fewer instructions per step in both
// pass1 and pass3 (~8% of the issue-bound instruction stream).
// f32x2 packing (R5/R7) abandoned: FFMA2 doubles fma-pipe cycles/instr.

#define T_LEN  4096
#define NTHR   128
#define HALF   (T_LEN / 2)        // 2048 steps per phase
#define F4C    8                  // input float4 per chunk per half
#define O4C    4                  // output float4 per chunk per half

namespace sm_consts {
constexpr double Cd = 0.1, dd = 0.01;
// alpha(k) = 1 + AL1*k + AL2*k^2   (I-component of deg-4 Taylor of exp(dt B))
// beta(k)  = BE0 + BE1*k           (B-component)
constexpr double AL1d = -dd*dd/2.0 + Cd*dd*dd*dd/6.0 - Cd*Cd*dd*dd*dd*dd/24.0;
constexpr double AL2d = dd*dd*dd*dd/24.0;
constexpr double BE0d = dd - Cd*dd*dd/2.0 + Cd*Cd*dd*dd*dd/6.0 - Cd*Cd*Cd*dd*dd*dd*dd/24.0;
constexpr double BE1d = -dd*dd*dd/6.0 + Cd*dd*dd*dd*dd/12.0;
// g = c0(k)*e1 + c1(k)*B*e1, B*e1 = (-C,1):  g1 = c0 - C*c1, g2 = c1
// c0 = dt*(1 - dt^2 k/6 + dt^3 C k/24)
// c1 = dt*(dt/2 - dt^2 C/6 + dt^3 (C^2 - k)/24)
constexpr double C00 = dd;
constexpr double C01 = dd*(-dd*dd/6.0 + dd*dd*dd*Cd/24.0);
constexpr double C10 = dd*(dd/2.0 - dd*dd*Cd/6.0 + dd*dd*dd*Cd*Cd/24.0);
constexpr double C11 = dd*(-dd*dd*dd/24.0);

constexpr float AL1 = (float)AL1d;
constexpr float AL2 = (float)AL2d;
constexpr float BE0 = (float)BE0d;
constexpr float BE1 = (float)BE1d;
constexpr float KG10 = (float)(C00 - Cd*C10);   // g1 = KG10 + KG11*k
constexpr float KG11 = (float)(C01 - Cd*C11);
constexpr float KG20 = (float)C10;              // g2 = KG20 + KG21*k
constexpr float KG21 = (float)C11;
constexpr float CF   = 0.1f;
}  // namespace sm_consts

struct Aff { float a11, a12, a21, a22, b1, b2; };

__device__ __forceinline__ Aff compose(const Aff& n, const Aff& o) {
    Aff r;
    r.a11 = fmaf(n.a11, o.a11, n.a12 * o.a21);
    r.a12 = fmaf(n.a11, o.a12, n.a12 * o.a22);
    r.a21 = fmaf(n.a21, o.a11, n.a22 * o.a21);
    r.a22 = fmaf(n.a21, o.a12, n.a22 * o.a22);
    r.b1  = fmaf(n.a11, o.b1, fmaf(n.a12, o.b2, n.b1));
    r.b2  = fmaf(n.a21, o.b1, fmaf(n.a22, o.b2, n.b2));
    return r;
}

__device__ __forceinline__ Aff step_map(float k, float F) {
    using namespace sm_consts;
    Aff s;
    float al = fmaf(fmaf(AL2, k, AL1), k, 1.0f);   // alpha (2 FMA)
    float be = fmaf(BE1, k, BE0);                  // beta  (1 FMA)
    s.a11 = fmaf(-CF, be, al);                     // alpha - C*beta
    s.a12 = -k * be;                               // (neg folds into FMUL)
    s.a21 = be;
    s.a22 = al;
    s.b1 = F * fmaf(KG11, k, KG10);
    s.b2 = F * fmaf(KG21, k, KG20);
    return s;
}

// advance state, return xddot for this step (computed from NEW state)
__device__ __forceinline__ float step_state(float k, float F, float& v, float& x) {
    using namespace sm_consts;
    float al = fmaf(fmaf(AL2, k, AL1), k, 1.0f);
    float be = fmaf(BE1, k, BE0);
    float A11 = fmaf(-CF, be, al);
    float A12 = -k * be;
    float g1  = fmaf(KG11, k, KG10);
    float g2  = fmaf(KG21, k, KG20);
    float vn = fmaf(A11, v, fmaf(A12, x, F * g1));
    float xn = fmaf(be,  v, fmaf(al,  x, F * g2));
    v = vn; x = xn;
    return fmaf(-k, xn, fmaf(-CF, vn, F));
}

__device__ __forceinline__ Aff shfl_up_aff(const Aff& m, int off) {
    Aff r;
    r.a11 = __shfl_up_sync(0xffffffffu, m.a11, off);
    r.a12 = __shfl_up_sync(0xffffffffu, m.a12, off);
    r.a21 = __shfl_up_sync(0xffffffffu, m.a21, off);
    r.a22 = __shfl_up_sync(0xffffffffu, m.a22, off);
    r.b1  = __shfl_up_sync(0xffffffffu, m.b1,  off);
    r.b2  = __shfl_up_sync(0xffffffffu, m.b2,  off);
    return r;
}

// smem slot for (chunk c, float4 offset o): XOR swizzle keeps per-chunk
// strided reads conflict-free per 8-lane LDS.128 phase.
__device__ __forceinline__ int slot(int c, int o) {
    return c * F4C + (o ^ (c & 7));
}

__global__ void __launch_bounds__(NTHR, 10)
spring_scan_kernel(const float* __restrict__ in,
                   const float* __restrict__ vinit,
                   const float* __restrict__ xinit,
                   float* __restrict__ out) {
    __shared__ float4 buf[NTHR * F4C];     // 16 KB half-row tile
    __shared__ Aff wsum[NTHR / 32];

    const int b = blockIdx.x;
    const int l = threadIdx.x;
    const int lane = l & 31;
    const int w = l >> 5;

    const float4* gin  = reinterpret_cast<const float4*>(in + (long)b * T_LEN * 2);
    float4*       gout = reinterpret_cast<float4*>(out + (long)b * T_LEN);

    float vh = vinit[b], xh = xinit[b];    // state entering current half

#pragma unroll 1
    for (int half = 0; half < 2; half++) {
        const float4* gin_h  = gin  + half * (HALF / 2);   // 1024 float4 per half
        float4*       gout_h = gout + half * (HALF / 4);   // 512 float4 per half

        // ---- Stage: coalesced global -> swizzled smem ----
#pragma unroll
        for (int r = 0; r < F4C; r++) {
            int idx = r * NTHR + l;
            buf[slot(idx >> 3, idx & 7)] = gin_h[idx];
        }
        __syncthreads();

        // ---- Pass 1: compose this thread's 16-step chunk map ----
        Aff M = {1.f, 0.f, 0.f, 1.f, 0.f, 0.f};
#pragma unroll 4
        for (int o = 0; o < F4C; o++) {
            float4 d = buf[slot(l, o)];
            M = compose(step_map(d.x, d.y), M);
            M = compose(step_map(d.z, d.w), M);
        }

        // ---- Pass 2: block-wide scan ----
#pragma unroll
        for (int off = 1; off < 32; off <<= 1) {
            Aff o = shfl_up_aff(M, off);
            if (lane >= off) M = compose(M, o);
        }

        if (lane == 31) wsum[w] = M;
        __syncthreads();

        // prefix over preceding warps + total half map (for the carry)
        Aff pre    = {1.f, 0.f, 0.f, 1.f, 0.f, 0.f};
        Aff preAll = {1.f, 0.f, 0.f, 1.f, 0.f, 0.f};
#pragma unroll
        for (int j = 0; j < NTHR / 32; j++) {
            if (j == w) pre = preAll;
            preAll = compose(wsum[j], preAll);
        }

        Aff eo = shfl_up_aff(M, 1);
        Aff excl;
        if (lane == 0) { excl.a11 = 1.f; excl.a12 = 0.f; excl.a21 = 0.f;
                         excl.a22 = 1.f; excl.b1 = 0.f;  excl.b2 = 0.f; }
        else           { excl = eo; }

        Aff tot = compose(excl, pre);      // exclusive prefix within half

        // state entering this thread's chunk
        float v = fmaf(tot.a11, vh, fmaf(tot.a12, xh, tot.b1));
        float x = fmaf(tot.a21, vh, fmaf(tot.a22, xh, tot.b2));

        // carry: state entering the next half
        float vh2 = fmaf(preAll.a11, vh, fmaf(preAll.a12, xh, preAll.b1));
        float xh2 = fmaf(preAll.a21, vh, fmaf(preAll.a22, xh, preAll.b2));
        vh = vh2; xh = xh2;

        // ---- Pass 3: replay chunk, write xddot in place ----
        // Output float4 j consumes input float4s 2j,2j+1; overwrites slot j
        // (j <= 2j: already consumed). Chunks are thread-private, no hazard.
#pragma unroll 2
        for (int j = 0; j < O4C; j++) {
            float4 d0 = buf[slot(l, 2 * j)];
            float4 d1 = buf[slot(l, 2 * j + 1)];
            float4 o4;
            o4.x = step_state(d0.x, d0.y, v, x);
            o4.y = step_state(d0.z, d0.w, v, x);
            o4.z = step_state(d1.x, d1.y, v, x);
            o4.w = step_state(d1.z, d1.w, v, x);
            buf[slot(l, j)] = o4;
        }
        __syncthreads();

        // ---- Drain: swizzled smem -> coalesced global store ----
#pragma unroll
        for (int r = 0; r < O4C; r++) {
            int idx = r * NTHR + l;
            gout_h[idx] = buf[slot(idx >> 2, idx & 3)];
        }
        if (half == 0) __syncthreads();    // buf + wsum reuse in next half
    }
}

extern "C" void kernel_launch(void* const* d_in, const int* in_sizes, int n_in,
                              void* d_out, int out_size) {
    const float* in = (const float*)d_in[0];       // (B, T, 2) float32
    const float* vi = (const float*)d_in[1];       // (B, 1)
    const float* xi = (const float*)d_in[2];       // (B, 1)
    float* out = (float*)d_out;                    // (B, T, 1) float32
    const int B = in_sizes[1];                     // 4096
    spring_scan_kernel<<<B, NTHR>>>(in, vi, xi, out);
}